// round 7
// baseline (speedup 1.0000x reference)
#include <cuda_runtime.h>

// ColorQuantizer: out[pix] = PALETTE[argmin_j | relu(x@W1+b1)@W2+b2 - c_j |^2]
// Straight-through output == hard palette lookup; softmax/sqrt/cdist drop out.
//
// R6: scalar fp32 core (R1, proven fma-pipe-saturated at 94.7us) plus:
//  - shifted-palette sparse scores: argmin invariant to +const/pixel; with
//    C' = C+1, 21 of 48 channel terms are exactly zero -> 27 imm-FFMA/px.
//  - fp64-pipe offload: first layer of 6/32 hidden units on DFMA (idle pipe,
//    MORE accurate than f32), removing 18 rt2-FFMA/px from the saturated pipe.
//  - b2 folded into accumulator init.

#define HW    262144u       // 512*512
#define NF32  26            // hidden units on the f32 fma pipe
#define NF64  6             // hidden units offloaded to the fp64 pipe
#define NTHR  (32u * HW / 4u)   // 2,097,152 threads, 4 px each

#define PV(v) ((float)(v) / 255.0f * 2.0f - 1.0f)
#define P3(a,b,c) {PV(a), PV(b), PV(c)}
static __device__ constexpr float PAL[16][3] = {
    P3(0,0,0),       P3(255,255,255), P3(255,0,0),     P3(0,255,0),
    P3(0,0,255),     P3(255,255,0),   P3(255,0,255),   P3(0,255,255),
    P3(128,128,128), P3(128,0,0),     P3(0,128,0),     P3(0,0,128),
    P3(128,128,0),   P3(128,0,128),   P3(0,128,128),   P3(192,192,192)
};

// Per f32 hidden unit k: [W1[0][k], W1[1][k], W1[2][k], b1[k], W2[k][0..2], 0]
__device__ float  g_w[32 * 8];
__device__ double g_w64[NF64 * 4];   // first-layer weights+bias for offloaded units
__device__ float  g_b2[4];

__global__ void prep_kernel(const float* __restrict__ W1, const float* __restrict__ b1,
                            const float* __restrict__ W2, const float* __restrict__ b2) {
    int k = threadIdx.x;
    if (k < 32) {
        float* w = &g_w[k * 8];
        w[0] = W1[0 * 32 + k];
        w[1] = W1[1 * 32 + k];
        w[2] = W1[2 * 32 + k];
        w[3] = b1[k];
        w[4] = W2[k * 3 + 0];
        w[5] = W2[k * 3 + 1];
        w[6] = W2[k * 3 + 2];
        w[7] = 0.0f;
    }
    if (k >= NF32 && k < 32) {          // units 26..31 -> fp64 copies
        int m = k - NF32;
        g_w64[m * 4 + 0] = (double)W1[0 * 32 + k];
        g_w64[m * 4 + 1] = (double)W1[1 * 32 + k];
        g_w64[m * 4 + 2] = (double)W1[2 * 32 + k];
        g_w64[m * 4 + 3] = (double)b1[k];
    }
    if (k < 3) g_b2[k] = b2[k];
    if (k == 3) g_b2[3] = 0.0f;
}

__global__ __launch_bounds__(256) void cq_kernel(const float* __restrict__ x,
                                                 float* __restrict__ out) {
    __shared__ float4 sW[64];          // 32 units x 2 float4
    __shared__ double sW64[NF64 * 4];  // 6 units x 4 doubles
    __shared__ float4 spal4[16];       // palette gather LUT

    int tid = threadIdx.x;
    if (tid < 64) sW[tid] = reinterpret_cast<const float4*>(g_w)[tid];
    if (tid >= 64 && tid < 64 + NF64 * 2) {
        int m = tid - 64;              // 12 x double2
        reinterpret_cast<double2*>(sW64)[m] = reinterpret_cast<const double2*>(g_w64)[m];
    }
    if (tid >= 96 && tid < 112) {
        int j = tid - 96;
        spal4[j] = make_float4(PAL[j][0], PAL[j][1], PAL[j][2], 0.0f);
    }
    __syncthreads();

    unsigned q = blockIdx.x * 256u + tid;      // quad index, 4 consecutive pixels
    unsigned b = q >> 16;                      // batch = q / (HW/4)
    unsigned r = (q & 65535u) << 2;            // pixel offset within plane

    const float* base = x + (size_t)b * 3 * HW + r;
    float4 ch0 = *reinterpret_cast<const float4*>(base);
    float4 ch1 = *reinterpret_cast<const float4*>(base + HW);
    float4 ch2 = *reinterpret_cast<const float4*>(base + 2 * HW);

    float X0[4] = {ch0.x, ch0.y, ch0.z, ch0.w};
    float X1[4] = {ch1.x, ch1.y, ch1.z, ch1.w};
    float X2[4] = {ch2.x, ch2.y, ch2.z, ch2.w};
    // fp64 copies of the inputs for the offloaded units (exact conversion)
    double XD0[4], XD1[4], XD2[4];
    #pragma unroll
    for (int i = 0; i < 4; i++) {
        XD0[i] = (double)X0[i];
        XD1[i] = (double)X1[i];
        XD2[i] = (double)X2[i];
    }

    float b2x = __ldg(&g_b2[0]);
    float b2y = __ldg(&g_b2[1]);
    float b2z = __ldg(&g_b2[2]);
    float p0[4] = {b2x, b2x, b2x, b2x};   // b2 folded into init
    float p1[4] = {b2y, b2y, b2y, b2y};
    float p2[4] = {b2z, b2z, b2z, b2z};

    // f32 units 0..25 on the fma pipe
    #pragma unroll
    for (int k = 0; k < NF32; k++) {
        float4 wa = sW[2 * k];       // W1 row-for-unit + b1
        float4 wb = sW[2 * k + 1];   // W2 row
        #pragma unroll
        for (int i = 0; i < 4; i++) {
            float a = fmaf(X0[i], wa.x, fmaf(X1[i], wa.y, fmaf(X2[i], wa.z, wa.w)));
            float h = fmaxf(a, 0.0f);
            p0[i] = fmaf(h, wb.x, p0[i]);
            p1[i] = fmaf(h, wb.y, p1[i]);
            p2[i] = fmaf(h, wb.z, p2[i]);
        }
    }

    // f64 units 26..31: first layer on the (idle) fp64 pipe, relu + second
    // layer back in f32. fp64 on f32 data is exact-or-better; decision noise
    // stays at the ~1e-7 level already proven flip-free.
    #pragma unroll
    for (int m = 0; m < NF64; m++) {
        double w0 = sW64[m * 4 + 0], w1 = sW64[m * 4 + 1];
        double w2 = sW64[m * 4 + 2], bb = sW64[m * 4 + 3];
        float4 wb = sW[2 * (NF32 + m) + 1];   // W2 row (f32)
        #pragma unroll
        for (int i = 0; i < 4; i++) {
            double a = fma(XD0[i], w0, fma(XD1[i], w1, fma(XD2[i], w2, bb)));
            float h = fmaxf(__double2float_rn(a), 0.0f);
            p0[i] = fmaf(h, wb.x, p0[i]);
            p1[i] = fmaf(h, wb.y, p1[i]);
            p2[i] = fmaf(h, wb.z, p2[i]);
        }
    }

    float r0[4], r1[4], r2[4];
    #pragma unroll
    for (int i = 0; i < 4; i++) {
        float q0 = p0[i], q1 = p1[i], q2 = p2[i];

        // Shifted-palette scores: s''_j = -2 q.(C_j + 1) + |C_j|^2.
        // Adding 2(q0+q1+q2) per pixel doesn't change argmin; channels with
        // byte 0 have C+1 == 0 exactly and their FFMA vanishes at compile time.
        // j = 0 is (0,0,0): s''_0 == |(-1,-1,-1)|^2 == 3 exactly.
        int   bi   = 0;
        float best = 3.0f;
        #pragma unroll
        for (int j = 1; j < 16; j++) {
            const float m0  = -2.0f * (PAL[j][0] + 1.0f);
            const float m1  = -2.0f * (PAL[j][1] + 1.0f);
            const float m2  = -2.0f * (PAL[j][2] + 1.0f);
            const float csq = PAL[j][0] * PAL[j][0] + PAL[j][1] * PAL[j][1]
                            + PAL[j][2] * PAL[j][2];
            float s = csq;
            if (m2 != 0.0f) s = fmaf(q2, m2, s);   // constexpr-folded guards
            if (m1 != 0.0f) s = fmaf(q1, m1, s);
            if (m0 != 0.0f) s = fmaf(q0, m0, s);
            if (s < best) { best = s; bi = j; }    // strict <: first-index ties
        }
        float4 col = spal4[bi];
        r0[i] = col.x; r1[i] = col.y; r2[i] = col.z;
    }

    float* obase = out + (size_t)b * 3 * HW + r;
    *reinterpret_cast<float4*>(obase)          = make_float4(r0[0], r0[1], r0[2], r0[3]);
    *reinterpret_cast<float4*>(obase + HW)     = make_float4(r1[0], r1[1], r1[2], r1[3]);
    *reinterpret_cast<float4*>(obase + 2 * HW) = make_float4(r2[0], r2[1], r2[2], r2[3]);
}

extern "C" void kernel_launch(void* const* d_in, const int* in_sizes, int n_in,
                              void* d_out, int out_size) {
    const float* x  = (const float*)d_in[0];
    const float* W1 = (const float*)d_in[1];
    const float* b1 = (const float*)d_in[2];
    const float* W2 = (const float*)d_in[3];
    const float* b2 = (const float*)d_in[4];
    float* out = (float*)d_out;

    prep_kernel<<<1, 32>>>(W1, b1, W2, b2);
    cq_kernel<<<NTHR / 256, 256>>>(x, out);
}

// round 8
// speedup vs baseline: 4.1298x; 4.1298x over previous
#include <cuda_runtime.h>

// ColorQuantizer: out[pix] = PALETTE[argmin_j | relu(x@W1+b1)@W2+b2 - c_j |^2]
// Straight-through output == hard palette lookup; softmax/sqrt/cdist drop out.
//
// R8: R1's proven fma-pipe-saturated scalar core (94.7us), plus only the
// validated-sound deltas:
//  - shifted-palette sparse scores: argmin invariant under +2(q0+q1+q2);
//    C' = C+1 makes 21/48 channel terms exactly zero -> 27 imm-FFMA/px (rt1).
//  - b2 folded into the accumulator init (removes 3 FADD/px from fma pipe).
//  - prep kernel deleted: weights staged into shared directly from raw inputs.
// fp64 offload REMOVED: B300 DFMA rt ~18.4 cyc/warp-op/SM made R7 3x slower.

#define HW    262144u            // 512*512
#define NTHR  (32u * HW / 4u)    // 2,097,152 threads, 4 px each

#define PV(v) ((float)(v) / 255.0f * 2.0f - 1.0f)
#define P3(a,b,c) {PV(a), PV(b), PV(c)}
static __device__ constexpr float PAL[16][3] = {
    P3(0,0,0),       P3(255,255,255), P3(255,0,0),     P3(0,255,0),
    P3(0,0,255),     P3(255,255,0),   P3(255,0,255),   P3(0,255,255),
    P3(128,128,128), P3(128,0,0),     P3(0,128,0),     P3(0,0,128),
    P3(128,128,0),   P3(128,0,128),   P3(0,128,128),   P3(192,192,192)
};

__global__ __launch_bounds__(256) void cq_kernel(const float* __restrict__ x,
                                                 const float* __restrict__ W1,
                                                 const float* __restrict__ b1,
                                                 const float* __restrict__ W2,
                                                 const float* __restrict__ b2,
                                                 float* __restrict__ out) {
    __shared__ float4 sW[64];      // unit k: [W1[0][k],W1[1][k],W1[2][k],b1[k]]
                                   //         [W2[k][0],W2[k][1],W2[k][2], 0 ]
    __shared__ float4 spal4[16];   // palette gather LUT
    __shared__ float  sB2[4];

    int tid = threadIdx.x;
    if (tid < 32) {                // stage weights straight from global inputs
        sW[2 * tid]     = make_float4(W1[tid], W1[32 + tid], W1[64 + tid], b1[tid]);
        sW[2 * tid + 1] = make_float4(W2[tid * 3], W2[tid * 3 + 1], W2[tid * 3 + 2], 0.0f);
    }
    if (tid >= 32 && tid < 48) {
        int j = tid - 32;
        spal4[j] = make_float4(PAL[j][0], PAL[j][1], PAL[j][2], 0.0f);
    }
    if (tid >= 48 && tid < 51) sB2[tid - 48] = b2[tid - 48];
    if (tid == 51) sB2[3] = 0.0f;
    __syncthreads();

    unsigned q = blockIdx.x * 256u + tid;      // quad index, 4 consecutive pixels
    unsigned b = q >> 16;                      // batch = q / (HW/4)
    unsigned r = (q & 65535u) << 2;            // pixel offset within plane

    const float* base = x + (size_t)b * 3 * HW + r;
    float4 ch0 = *reinterpret_cast<const float4*>(base);
    float4 ch1 = *reinterpret_cast<const float4*>(base + HW);
    float4 ch2 = *reinterpret_cast<const float4*>(base + 2 * HW);

    float X0[4] = {ch0.x, ch0.y, ch0.z, ch0.w};
    float X1[4] = {ch1.x, ch1.y, ch1.z, ch1.w};
    float X2[4] = {ch2.x, ch2.y, ch2.z, ch2.w};

    float b2x = sB2[0], b2y = sB2[1], b2z = sB2[2];
    float p0[4] = {b2x, b2x, b2x, b2x};        // b2 folded into init
    float p1[4] = {b2y, b2y, b2y, b2y};
    float p2[4] = {b2z, b2z, b2z, b2z};

    // MLP: p = relu(x @ W1 + b1) @ W2 + b2(in init)  — all on the fma pipe
    #pragma unroll
    for (int k = 0; k < 32; k++) {
        float4 wa = sW[2 * k];
        float4 wb = sW[2 * k + 1];
        #pragma unroll
        for (int i = 0; i < 4; i++) {
            float a = fmaf(X0[i], wa.x, fmaf(X1[i], wa.y, fmaf(X2[i], wa.z, wa.w)));
            float h = fmaxf(a, 0.0f);          // FMNMX: alu pipe
            p0[i] = fmaf(h, wb.x, p0[i]);
            p1[i] = fmaf(h, wb.y, p1[i]);
            p2[i] = fmaf(h, wb.z, p2[i]);
        }
    }

    float r0[4], r1[4], r2[4];
    #pragma unroll
    for (int i = 0; i < 4; i++) {
        float q0 = p0[i], q1 = p1[i], q2 = p2[i];

        // Shifted-palette scores: s_j = -2 q.(C_j + 1) + |C_j|^2.
        // Adding 2(q0+q1+q2) (const in j) preserves argmin; zero-byte channels
        // have C+1 == 0 exactly -> their FFMA folds away at compile time.
        // j = 0 is (0,0,0): s_0 == 3 exactly.
        int   bi   = 0;
        float best = 3.0f;
        #pragma unroll
        for (int j = 1; j < 16; j++) {
            const float m0  = -2.0f * (PAL[j][0] + 1.0f);
            const float m1  = -2.0f * (PAL[j][1] + 1.0f);
            const float m2  = -2.0f * (PAL[j][2] + 1.0f);
            const float csq = PAL[j][0] * PAL[j][0] + PAL[j][1] * PAL[j][1]
                            + PAL[j][2] * PAL[j][2];
            float s = csq;
            if (m2 != 0.0f) s = fmaf(q2, m2, s);   // constexpr-folded guards;
            if (m1 != 0.0f) s = fmaf(q1, m1, s);   // survivors are imm-FFMA (rt1)
            if (m0 != 0.0f) s = fmaf(q0, m0, s);
            if (s < best) { best = s; bi = j; }    // strict <: first-index ties
        }
        float4 col = spal4[bi];
        r0[i] = col.x; r1[i] = col.y; r2[i] = col.z;
    }

    float* obase = out + (size_t)b * 3 * HW + r;
    *reinterpret_cast<float4*>(obase)          = make_float4(r0[0], r0[1], r0[2], r0[3]);
    *reinterpret_cast<float4*>(obase + HW)     = make_float4(r1[0], r1[1], r1[2], r1[3]);
    *reinterpret_cast<float4*>(obase + 2 * HW) = make_float4(r2[0], r2[1], r2[2], r2[3]);
}

extern "C" void kernel_launch(void* const* d_in, const int* in_sizes, int n_in,
                              void* d_out, int out_size) {
    const float* x  = (const float*)d_in[0];
    const float* W1 = (const float*)d_in[1];
    const float* b1 = (const float*)d_in[2];
    const float* W2 = (const float*)d_in[3];
    const float* b2 = (const float*)d_in[4];
    float* out = (float*)d_out;

    cq_kernel<<<NTHR / 256, 256>>>(x, W1, b1, W2, b2, out);
}

// round 10
// speedup vs baseline: 4.4172x; 1.0696x over previous
#include <cuda_runtime.h>

// ColorQuantizer: out[pix] = PALETTE[argmin_j | relu(x@W1+b1)@W2+b2 - c_j |^2]
// Straight-through output == hard palette lookup; softmax/sqrt/cdist drop out.
//
// R9 (resubmit): attack the RF-banking rt2 wall. 3-reg FFMA is rt2 only because
// 3 distinct GPR sources collide in the even/odd register banks. Weights are
// warp-uniform: move them to __constant__ (via graph-capturable async D2D
// memcpyToSymbol) so ptxas emits LDCU -> uniform regs -> FFMA with a UR operand
// = 2 distinct GPRs = rt1 = 2x fma-pipe throughput on the MLP.
// Palette gather stays in shared (per-lane dynamic index must not hit cmem).
// Scores keep the shifted-palette sparse form (27 imm-FFMA/px, rt1).
// Argmin stays exact FSETP/SEL (mantissa-key trick rejected: ~10 flips ~ fail).

#define HW    262144u            // 512*512
#define NTHR  (32u * HW / 4u)    // 2,097,152 threads, 4 px each

#define PV(v) ((float)(v) / 255.0f * 2.0f - 1.0f)
#define P3(a,b,c) {PV(a), PV(b), PV(c)}
static __device__ constexpr float PAL[16][3] = {
    P3(0,0,0),       P3(255,255,255), P3(255,0,0),     P3(0,255,0),
    P3(0,0,255),     P3(255,255,0),   P3(255,0,255),   P3(0,255,255),
    P3(128,128,128), P3(128,0,0),     P3(0,128,0),     P3(0,0,128),
    P3(128,128,0),   P3(128,0,128),   P3(0,128,128),   P3(192,192,192)
};

// Runtime weights in constant memory -> LDCU/uniform-register operands.
__constant__ float cW1[96];   // [3][32] row-major, as given
__constant__ float cb1[32];
__constant__ float cW2[96];   // [32][3] row-major, as given
__constant__ float cb2[3];

__global__ __launch_bounds__(256) void cq_kernel(const float* __restrict__ x,
                                                 float* __restrict__ out) {
    __shared__ float4 spal4[16];   // palette gather LUT (per-lane dynamic index)

    int tid = threadIdx.x;
    if (tid < 16)
        spal4[tid] = make_float4(PAL[tid][0], PAL[tid][1], PAL[tid][2], 0.0f);
    __syncthreads();

    unsigned q = blockIdx.x * 256u + tid;      // quad index, 4 consecutive pixels
    unsigned b = q >> 16;                      // batch = q / (HW/4)
    unsigned r = (q & 65535u) << 2;            // pixel offset within plane

    const float* base = x + (size_t)b * 3 * HW + r;
    float4 ch0 = *reinterpret_cast<const float4*>(base);
    float4 ch1 = *reinterpret_cast<const float4*>(base + HW);
    float4 ch2 = *reinterpret_cast<const float4*>(base + 2 * HW);

    float X0[4] = {ch0.x, ch0.y, ch0.z, ch0.w};
    float X1[4] = {ch1.x, ch1.y, ch1.z, ch1.w};
    float X2[4] = {ch2.x, ch2.y, ch2.z, ch2.w};

    float b2x = cb2[0], b2y = cb2[1], b2z = cb2[2];
    float p0[4] = {b2x, b2x, b2x, b2x};        // b2 folded into init
    float p1[4] = {b2y, b2y, b2y, b2y};
    float p2[4] = {b2z, b2z, b2z, b2z};

    // MLP: p = relu(x @ W1 + b1) @ W2 (+b2 in init). All weight reads are at
    // compile-time offsets (fully unrolled) -> warp-uniform LDCU -> UR operand.
    #pragma unroll
    for (int k = 0; k < 32; k++) {
        float wx = cW1[k], wy = cW1[32 + k], wz = cW1[64 + k], bb = cb1[k];
        float u0 = cW2[3 * k], u1 = cW2[3 * k + 1], u2 = cW2[3 * k + 2];
        #pragma unroll
        for (int i = 0; i < 4; i++) {
            float a = fmaf(X0[i], wx, fmaf(X1[i], wy, fmaf(X2[i], wz, bb)));
            float h = fmaxf(a, 0.0f);          // FMNMX: alu pipe
            p0[i] = fmaf(h, u0, p0[i]);
            p1[i] = fmaf(h, u1, p1[i]);
            p2[i] = fmaf(h, u2, p2[i]);
        }
    }

    float r0[4], r1[4], r2[4];
    #pragma unroll
    for (int i = 0; i < 4; i++) {
        float q0 = p0[i], q1 = p1[i], q2 = p2[i];

        // Shifted-palette scores: s_j = -2 q.(C_j + 1) + |C_j|^2.
        // +2(q0+q1+q2) (const in j) preserves argmin; zero-byte channels give
        // C+1 == 0 exactly -> FFMA folds away. j=0 score == 3.0 exactly.
        int   bi   = 0;
        float best = 3.0f;
        #pragma unroll
        for (int j = 1; j < 16; j++) {
            const float m0  = -2.0f * (PAL[j][0] + 1.0f);
            const float m1  = -2.0f * (PAL[j][1] + 1.0f);
            const float m2  = -2.0f * (PAL[j][2] + 1.0f);
            const float csq = PAL[j][0] * PAL[j][0] + PAL[j][1] * PAL[j][1]
                            + PAL[j][2] * PAL[j][2];
            float s = csq;
            if (m2 != 0.0f) s = fmaf(q2, m2, s);   // constexpr-folded guards;
            if (m1 != 0.0f) s = fmaf(q1, m1, s);   // survivors are imm-FFMA (rt1)
            if (m0 != 0.0f) s = fmaf(q0, m0, s);
            if (s < best) { best = s; bi = j; }    // exact: strict <, first-index
        }
        float4 col = spal4[bi];
        r0[i] = col.x; r1[i] = col.y; r2[i] = col.z;
    }

    float* obase = out + (size_t)b * 3 * HW + r;
    *reinterpret_cast<float4*>(obase)          = make_float4(r0[0], r0[1], r0[2], r0[3]);
    *reinterpret_cast<float4*>(obase + HW)     = make_float4(r1[0], r1[1], r1[2], r1[3]);
    *reinterpret_cast<float4*>(obase + 2 * HW) = make_float4(r2[0], r2[1], r2[2], r2[3]);
}

extern "C" void kernel_launch(void* const* d_in, const int* in_sizes, int n_in,
                              void* d_out, int out_size) {
    const float* x  = (const float*)d_in[0];
    float* out = (float*)d_out;

    // Device-to-device async copies into constant memory: graph-capturable,
    // no allocation. Ordered before the kernel on the captured stream.
    cudaMemcpyToSymbolAsync(cW1, d_in[1], 96 * sizeof(float), 0,
                            cudaMemcpyDeviceToDevice, 0);
    cudaMemcpyToSymbolAsync(cb1, d_in[2], 32 * sizeof(float), 0,
                            cudaMemcpyDeviceToDevice, 0);
    cudaMemcpyToSymbolAsync(cW2, d_in[3], 96 * sizeof(float), 0,
                            cudaMemcpyDeviceToDevice, 0);
    cudaMemcpyToSymbolAsync(cb2, d_in[4], 3 * sizeof(float), 0,
                            cudaMemcpyDeviceToDevice, 0);

    cq_kernel<<<NTHR / 256, 256>>>(x, out);
}

// round 11
// speedup vs baseline: 4.5820x; 1.0373x over previous
#include <cuda_runtime.h>

// ColorQuantizer: out[pix] = PALETTE[argmin_j | relu(x@W1+b1)@W2+b2 - c_j |^2]
// Straight-through output == hard palette lookup; softmax/sqrt/cdist drop out.
//
// R11: keep the proven R10 cq_kernel (84.5us: __constant__ weights -> LDCU ->
// UR-operand FFMA at rt1), but collapse the 4 memcpyToSymbol graph nodes
// (~9.8us of node overhead) into gather-kernel + ONE 908B memcpy node.

#define HW    262144u            // 512*512
#define NTHR  (32u * HW / 4u)    // 2,097,152 threads, 4 px each

#define PV(v) ((float)(v) / 255.0f * 2.0f - 1.0f)
#define P3(a,b,c) {PV(a), PV(b), PV(c)}
static __device__ constexpr float PAL[16][3] = {
    P3(0,0,0),       P3(255,255,255), P3(255,0,0),     P3(0,255,0),
    P3(0,0,255),     P3(255,255,0),   P3(255,0,255),   P3(0,255,255),
    P3(128,128,128), P3(128,0,0),     P3(0,128,0),     P3(0,0,128),
    P3(128,128,0),   P3(128,0,128),   P3(0,128,128),   P3(192,192,192)
};

// Single constant block: [0..95] W1 ([3][32]), [96..127] b1,
//                        [128..223] W2 ([32][3]), [224..226] b2, [227] pad.
#define OFF_W1 0
#define OFF_B1 96
#define OFF_W2 128
#define OFF_B2 224
__constant__ float cAll[228];
__device__   float g_stage[228];

__global__ void gather_kernel(const float* __restrict__ W1, const float* __restrict__ b1,
                              const float* __restrict__ W2, const float* __restrict__ b2) {
    int i = threadIdx.x;                       // 228 threads
    float v = 0.0f;
    if (i < 96)                    v = W1[i];
    else if (i < 128)              v = b1[i - 96];
    else if (i < 224)              v = W2[i - 128];
    else if (i < 227)              v = b2[i - 224];
    g_stage[i] = v;
}

__global__ __launch_bounds__(256) void cq_kernel(const float* __restrict__ x,
                                                 float* __restrict__ out) {
    __shared__ float4 spal4[16];   // palette gather LUT (per-lane dynamic index)

    int tid = threadIdx.x;
    if (tid < 16)
        spal4[tid] = make_float4(PAL[tid][0], PAL[tid][1], PAL[tid][2], 0.0f);
    __syncthreads();

    unsigned q = blockIdx.x * 256u + tid;      // quad index, 4 consecutive pixels
    unsigned b = q >> 16;                      // batch = q / (HW/4)
    unsigned r = (q & 65535u) << 2;            // pixel offset within plane

    const float* base = x + (size_t)b * 3 * HW + r;
    float4 ch0 = *reinterpret_cast<const float4*>(base);
    float4 ch1 = *reinterpret_cast<const float4*>(base + HW);
    float4 ch2 = *reinterpret_cast<const float4*>(base + 2 * HW);

    float X0[4] = {ch0.x, ch0.y, ch0.z, ch0.w};
    float X1[4] = {ch1.x, ch1.y, ch1.z, ch1.w};
    float X2[4] = {ch2.x, ch2.y, ch2.z, ch2.w};

    float b2x = cAll[OFF_B2 + 0], b2y = cAll[OFF_B2 + 1], b2z = cAll[OFF_B2 + 2];
    float p0[4] = {b2x, b2x, b2x, b2x};        // b2 folded into init
    float p1[4] = {b2y, b2y, b2y, b2y};
    float p2[4] = {b2z, b2z, b2z, b2z};

    // MLP: p = relu(x @ W1 + b1) @ W2 (+b2 in init). All weight reads are at
    // compile-time offsets (fully unrolled) -> warp-uniform LDCU -> UR operand
    // -> rt1 FFMA (proven in R10: 99.2 -> 84.5us).
    #pragma unroll
    for (int k = 0; k < 32; k++) {
        float wx = cAll[OFF_W1 + k], wy = cAll[OFF_W1 + 32 + k];
        float wz = cAll[OFF_W1 + 64 + k], bb = cAll[OFF_B1 + k];
        float u0 = cAll[OFF_W2 + 3 * k], u1 = cAll[OFF_W2 + 3 * k + 1];
        float u2 = cAll[OFF_W2 + 3 * k + 2];
        #pragma unroll
        for (int i = 0; i < 4; i++) {
            float a = fmaf(X0[i], wx, fmaf(X1[i], wy, fmaf(X2[i], wz, bb)));
            float h = fmaxf(a, 0.0f);          // FMNMX: alu pipe
            p0[i] = fmaf(h, u0, p0[i]);
            p1[i] = fmaf(h, u1, p1[i]);
            p2[i] = fmaf(h, u2, p2[i]);
        }
    }

    float r0[4], r1[4], r2[4];
    #pragma unroll
    for (int i = 0; i < 4; i++) {
        float q0 = p0[i], q1 = p1[i], q2 = p2[i];

        // Shifted-palette scores: s_j = -2 q.(C_j + 1) + |C_j|^2.
        // +2(q0+q1+q2) (const in j) preserves argmin; zero-byte channels give
        // C+1 == 0 exactly -> FFMA folds away. j=0 score == 3.0 exactly.
        int   bi   = 0;
        float best = 3.0f;
        #pragma unroll
        for (int j = 1; j < 16; j++) {
            const float m0  = -2.0f * (PAL[j][0] + 1.0f);
            const float m1  = -2.0f * (PAL[j][1] + 1.0f);
            const float m2  = -2.0f * (PAL[j][2] + 1.0f);
            const float csq = PAL[j][0] * PAL[j][0] + PAL[j][1] * PAL[j][1]
                            + PAL[j][2] * PAL[j][2];
            float s = csq;
            if (m2 != 0.0f) s = fmaf(q2, m2, s);   // constexpr-folded guards;
            if (m1 != 0.0f) s = fmaf(q1, m1, s);   // survivors are imm-FFMA (rt1)
            if (m0 != 0.0f) s = fmaf(q0, m0, s);
            if (s < best) { best = s; bi = j; }    // exact: strict <, first-index
        }
        float4 col = spal4[bi];
        r0[i] = col.x; r1[i] = col.y; r2[i] = col.z;
    }

    float* obase = out + (size_t)b * 3 * HW + r;
    *reinterpret_cast<float4*>(obase)          = make_float4(r0[0], r0[1], r0[2], r0[3]);
    *reinterpret_cast<float4*>(obase + HW)     = make_float4(r1[0], r1[1], r1[2], r1[3]);
    *reinterpret_cast<float4*>(obase + 2 * HW) = make_float4(r2[0], r2[1], r2[2], r2[3]);
}

extern "C" void kernel_launch(void* const* d_in, const int* in_sizes, int n_in,
                              void* d_out, int out_size) {
    const float* x  = (const float*)d_in[0];
    float* out = (float*)d_out;

    // Pack the 4 small weight tensors into one staging array (1 kernel node),
    // then a single D2D memcpy node into constant memory. Both capturable,
    // allocation-free, deterministic.
    gather_kernel<<<1, 228>>>((const float*)d_in[1], (const float*)d_in[2],
                              (const float*)d_in[3], (const float*)d_in[4]);

    void* stage_ptr = nullptr;
    cudaGetSymbolAddress(&stage_ptr, g_stage);   // address query only, no stream op
    cudaMemcpyToSymbolAsync(cAll, stage_ptr, 228 * sizeof(float), 0,
                            cudaMemcpyDeviceToDevice, 0);

    cq_kernel<<<NTHR / 256, 256>>>(x, out);
}

// round 12
// speedup vs baseline: 4.7217x; 1.0305x over previous
#include <cuda_runtime.h>

// ColorQuantizer: out[pix] = PALETTE[argmin_j | relu(x@W1+b1)@W2+b2 - c_j |^2]
// Straight-through output == hard palette lookup; softmax/sqrt/cdist drop out.
//
// R12: proven R10/R11 core (__constant__ weights -> LDCU -> UR-operand FFMA at
// rt1; shifted-palette sparse scores; 3-node graph) + 8 px/thread: halves
// per-thread fixed cost and doubles independent chains per warp to cover LDG
// latency and the serial argmin FSETP chains (issue was 83.7% at 4px).

#define HW    262144u            // 512*512
#define NTHR8 (32u * HW / 8u)    // 1,048,576 threads, 8 px each

#define PV(v) ((float)(v) / 255.0f * 2.0f - 1.0f)
#define P3(a,b,c) {PV(a), PV(b), PV(c)}
static __device__ constexpr float PAL[16][3] = {
    P3(0,0,0),       P3(255,255,255), P3(255,0,0),     P3(0,255,0),
    P3(0,0,255),     P3(255,255,0),   P3(255,0,255),   P3(0,255,255),
    P3(128,128,128), P3(128,0,0),     P3(0,128,0),     P3(0,0,128),
    P3(128,128,0),   P3(128,0,128),   P3(0,128,128),   P3(192,192,192)
};

// Single constant block: [0..95] W1 ([3][32]), [96..127] b1,
//                        [128..223] W2 ([32][3]), [224..226] b2, [227] pad.
#define OFF_W1 0
#define OFF_B1 96
#define OFF_W2 128
#define OFF_B2 224
__constant__ float cAll[228];
__device__   float g_stage[228];

__global__ void gather_kernel(const float* __restrict__ W1, const float* __restrict__ b1,
                              const float* __restrict__ W2, const float* __restrict__ b2) {
    int i = threadIdx.x;                       // 228 threads
    float v = 0.0f;
    if (i < 96)                    v = W1[i];
    else if (i < 128)              v = b1[i - 96];
    else if (i < 224)              v = W2[i - 128];
    else if (i < 227)              v = b2[i - 224];
    g_stage[i] = v;
}

__global__ __launch_bounds__(256) void cq_kernel(const float* __restrict__ x,
                                                 float* __restrict__ out) {
    __shared__ float4 spal4[16];   // palette gather LUT (per-lane dynamic index)

    int tid = threadIdx.x;
    if (tid < 16)
        spal4[tid] = make_float4(PAL[tid][0], PAL[tid][1], PAL[tid][2], 0.0f);
    __syncthreads();

    unsigned q = blockIdx.x * 256u + tid;      // 8-px group index
    unsigned b = q >> 15;                      // batch = q / (HW/8)
    unsigned r = (q & 32767u) << 3;            // pixel offset within plane

    const float* base = x + (size_t)b * 3 * HW + r;
    float X0[8], X1[8], X2[8];
    {
        float4 t;
        t = reinterpret_cast<const float4*>(base)[0];
        X0[0]=t.x; X0[1]=t.y; X0[2]=t.z; X0[3]=t.w;
        t = reinterpret_cast<const float4*>(base)[1];
        X0[4]=t.x; X0[5]=t.y; X0[6]=t.z; X0[7]=t.w;
        t = reinterpret_cast<const float4*>(base + HW)[0];
        X1[0]=t.x; X1[1]=t.y; X1[2]=t.z; X1[3]=t.w;
        t = reinterpret_cast<const float4*>(base + HW)[1];
        X1[4]=t.x; X1[5]=t.y; X1[6]=t.z; X1[7]=t.w;
        t = reinterpret_cast<const float4*>(base + 2 * HW)[0];
        X2[0]=t.x; X2[1]=t.y; X2[2]=t.z; X2[3]=t.w;
        t = reinterpret_cast<const float4*>(base + 2 * HW)[1];
        X2[4]=t.x; X2[5]=t.y; X2[6]=t.z; X2[7]=t.w;
    }

    float b2x = cAll[OFF_B2 + 0], b2y = cAll[OFF_B2 + 1], b2z = cAll[OFF_B2 + 2];
    float p0[8], p1[8], p2[8];
    #pragma unroll
    for (int i = 0; i < 8; i++) { p0[i] = b2x; p1[i] = b2y; p2[i] = b2z; }

    // MLP: p = relu(x @ W1 + b1) @ W2 (+b2 in init). Weight reads at
    // compile-time offsets -> warp-uniform LDCU -> UR operand -> rt1 FFMA.
    #pragma unroll
    for (int k = 0; k < 32; k++) {
        float wx = cAll[OFF_W1 + k], wy = cAll[OFF_W1 + 32 + k];
        float wz = cAll[OFF_W1 + 64 + k], bb = cAll[OFF_B1 + k];
        float u0 = cAll[OFF_W2 + 3 * k], u1 = cAll[OFF_W2 + 3 * k + 1];
        float u2 = cAll[OFF_W2 + 3 * k + 2];
        #pragma unroll
        for (int i = 0; i < 8; i++) {
            float a = fmaf(X0[i], wx, fmaf(X1[i], wy, fmaf(X2[i], wz, bb)));
            float h = fmaxf(a, 0.0f);          // FMNMX: alu pipe
            p0[i] = fmaf(h, u0, p0[i]);
            p1[i] = fmaf(h, u1, p1[i]);
            p2[i] = fmaf(h, u2, p2[i]);
        }
    }

    float r0[8], r1[8], r2[8];
    #pragma unroll
    for (int i = 0; i < 8; i++) {
        float q0 = p0[i], q1 = p1[i], q2 = p2[i];

        // Shifted-palette scores: s_j = -2 q.(C_j + 1) + |C_j|^2.
        // +2(q0+q1+q2) (const in j) preserves argmin; zero-byte channels give
        // C+1 == 0 exactly -> FFMA folds away. j=0 score == 3.0 exactly.
        int   bi   = 0;
        float best = 3.0f;
        #pragma unroll
        for (int j = 1; j < 16; j++) {
            const float m0  = -2.0f * (PAL[j][0] + 1.0f);
            const float m1  = -2.0f * (PAL[j][1] + 1.0f);
            const float m2  = -2.0f * (PAL[j][2] + 1.0f);
            const float csq = PAL[j][0] * PAL[j][0] + PAL[j][1] * PAL[j][1]
                            + PAL[j][2] * PAL[j][2];
            float s = csq;
            if (m2 != 0.0f) s = fmaf(q2, m2, s);   // constexpr-folded guards;
            if (m1 != 0.0f) s = fmaf(q1, m1, s);   // survivors are imm-FFMA (rt1)
            if (m0 != 0.0f) s = fmaf(q0, m0, s);
            if (s < best) { best = s; bi = j; }    // exact: strict <, first-index
        }
        float4 col = spal4[bi];
        r0[i] = col.x; r1[i] = col.y; r2[i] = col.z;
    }

    float* obase = out + (size_t)b * 3 * HW + r;
    reinterpret_cast<float4*>(obase)[0]          = make_float4(r0[0], r0[1], r0[2], r0[3]);
    reinterpret_cast<float4*>(obase)[1]          = make_float4(r0[4], r0[5], r0[6], r0[7]);
    reinterpret_cast<float4*>(obase + HW)[0]     = make_float4(r1[0], r1[1], r1[2], r1[3]);
    reinterpret_cast<float4*>(obase + HW)[1]     = make_float4(r1[4], r1[5], r1[6], r1[7]);
    reinterpret_cast<float4*>(obase + 2 * HW)[0] = make_float4(r2[0], r2[1], r2[2], r2[3]);
    reinterpret_cast<float4*>(obase + 2 * HW)[1] = make_float4(r2[4], r2[5], r2[6], r2[7]);
}

extern "C" void kernel_launch(void* const* d_in, const int* in_sizes, int n_in,
                              void* d_out, int out_size) {
    const float* x  = (const float*)d_in[0];
    float* out = (float*)d_out;

    gather_kernel<<<1, 228>>>((const float*)d_in[1], (const float*)d_in[2],
                              (const float*)d_in[3], (const float*)d_in[4]);

    void* stage_ptr = nullptr;
    cudaGetSymbolAddress(&stage_ptr, g_stage);   // address query only, no stream op
    cudaMemcpyToSymbolAsync(cAll, stage_ptr, 228 * sizeof(float), 0,
                            cudaMemcpyDeviceToDevice, 0);

    cq_kernel<<<NTHR8 / 256, 256>>>(x, out);
}

// round 13
// speedup vs baseline: 4.7251x; 1.0007x over previous
#include <cuda_runtime.h>

// ColorQuantizer: out[pix] = PALETTE[argmin_j | relu(x@W1+b1)@W2+b2 - c_j |^2]
// Straight-through output == hard palette lookup; softmax/sqrt/cdist drop out.
//
// R13: same proven core (__constant__ -> LDCU -> UR-operand rt1 FFMA; sparse
// shifted-palette scores; 8 px/thread; 3-node graph). Change: argmin becomes a
// balanced tournament (4-level tree, op-count identical, critical path 15->4)
// to attack the ~16% issue-idle; stores retire in two half-batches.

#define HW    262144u            // 512*512
#define NTHR8 (32u * HW / 8u)    // 1,048,576 threads, 8 px each

#define PV(v) ((float)(v) / 255.0f * 2.0f - 1.0f)
#define P3(a,b,c) {PV(a), PV(b), PV(c)}
static __device__ constexpr float PAL[16][3] = {
    P3(0,0,0),       P3(255,255,255), P3(255,0,0),     P3(0,255,0),
    P3(0,0,255),     P3(255,255,0),   P3(255,0,255),   P3(0,255,255),
    P3(128,128,128), P3(128,0,0),     P3(0,128,0),     P3(0,0,128),
    P3(128,128,0),   P3(128,0,128),   P3(0,128,128),   P3(192,192,192)
};

#define OFF_W1 0
#define OFF_B1 96
#define OFF_W2 128
#define OFF_B2 224
__constant__ float cAll[228];
__device__   float g_stage[228];

__global__ void gather_kernel(const float* __restrict__ W1, const float* __restrict__ b1,
                              const float* __restrict__ W2, const float* __restrict__ b2) {
    int i = threadIdx.x;                       // 228 threads
    float v = 0.0f;
    if (i < 96)                    v = W1[i];
    else if (i < 128)              v = b1[i - 96];
    else if (i < 224)              v = W2[i - 128];
    else if (i < 227)              v = b2[i - 224];
    g_stage[i] = v;
}

// Tournament node: keeps (score, idx) of the smaller score; on exact tie keeps
// the LEFT (lower-index) argument -> first-index-wins, matching the reference.
#define TMIN(sa, ia, sb, ib, so, io)  do { \
    bool _p = (sb) < (sa);                  \
    so = _p ? (sb) : (sa);                  \
    io = _p ? (ib) : (ia);                  \
} while (0)

__global__ __launch_bounds__(256) void cq_kernel(const float* __restrict__ x,
                                                 float* __restrict__ out) {
    __shared__ float4 spal4[16];   // palette gather LUT (per-lane dynamic index)

    int tid = threadIdx.x;
    if (tid < 16)
        spal4[tid] = make_float4(PAL[tid][0], PAL[tid][1], PAL[tid][2], 0.0f);
    __syncthreads();

    unsigned q = blockIdx.x * 256u + tid;      // 8-px group index
    unsigned b = q >> 15;                      // batch = q / (HW/8)
    unsigned r = (q & 32767u) << 3;            // pixel offset within plane

    const float* base = x + (size_t)b * 3 * HW + r;
    float X0[8], X1[8], X2[8];
    {
        float4 t;
        t = reinterpret_cast<const float4*>(base)[0];
        X0[0]=t.x; X0[1]=t.y; X0[2]=t.z; X0[3]=t.w;
        t = reinterpret_cast<const float4*>(base)[1];
        X0[4]=t.x; X0[5]=t.y; X0[6]=t.z; X0[7]=t.w;
        t = reinterpret_cast<const float4*>(base + HW)[0];
        X1[0]=t.x; X1[1]=t.y; X1[2]=t.z; X1[3]=t.w;
        t = reinterpret_cast<const float4*>(base + HW)[1];
        X1[4]=t.x; X1[5]=t.y; X1[6]=t.z; X1[7]=t.w;
        t = reinterpret_cast<const float4*>(base + 2 * HW)[0];
        X2[0]=t.x; X2[1]=t.y; X2[2]=t.z; X2[3]=t.w;
        t = reinterpret_cast<const float4*>(base + 2 * HW)[1];
        X2[4]=t.x; X2[5]=t.y; X2[6]=t.z; X2[7]=t.w;
    }

    float b2x = cAll[OFF_B2 + 0], b2y = cAll[OFF_B2 + 1], b2z = cAll[OFF_B2 + 2];
    float p0[8], p1[8], p2[8];
    #pragma unroll
    for (int i = 0; i < 8; i++) { p0[i] = b2x; p1[i] = b2y; p2[i] = b2z; }

    // MLP: weights at compile-time constant offsets -> LDCU -> UR operand -> rt1.
    #pragma unroll
    for (int k = 0; k < 32; k++) {
        float wx = cAll[OFF_W1 + k], wy = cAll[OFF_W1 + 32 + k];
        float wz = cAll[OFF_W1 + 64 + k], bb = cAll[OFF_B1 + k];
        float u0 = cAll[OFF_W2 + 3 * k], u1 = cAll[OFF_W2 + 3 * k + 1];
        float u2 = cAll[OFF_W2 + 3 * k + 2];
        #pragma unroll
        for (int i = 0; i < 8; i++) {
            float a = fmaf(X0[i], wx, fmaf(X1[i], wy, fmaf(X2[i], wz, bb)));
            float h = fmaxf(a, 0.0f);          // FMNMX: alu pipe
            p0[i] = fmaf(h, u0, p0[i]);
            p1[i] = fmaf(h, u1, p1[i]);
            p2[i] = fmaf(h, u2, p2[i]);
        }
    }

    float r0[8], r1[8], r2[8];
    #pragma unroll
    for (int i = 0; i < 8; i++) {
        float q0 = p0[i], q1 = p1[i], q2 = p2[i];

        // Shifted-palette scores: s_j = -2 q.(C_j+1) + |C_j|^2 (argmin-preserving;
        // zero-byte channels fold away; s_0 == 3.0 exactly). All 16 independent.
        float s[16];
        s[0] = 3.0f;
        #pragma unroll
        for (int j = 1; j < 16; j++) {
            const float m0  = -2.0f * (PAL[j][0] + 1.0f);
            const float m1  = -2.0f * (PAL[j][1] + 1.0f);
            const float m2  = -2.0f * (PAL[j][2] + 1.0f);
            const float csq = PAL[j][0] * PAL[j][0] + PAL[j][1] * PAL[j][1]
                            + PAL[j][2] * PAL[j][2];
            float v = csq;
            if (m2 != 0.0f) v = fmaf(q2, m2, v);
            if (m1 != 0.0f) v = fmaf(q1, m1, v);
            if (m0 != 0.0f) v = fmaf(q0, m0, v);
            s[j] = v;
        }

        // Balanced tournament: 8+4+2+1 compares, critical path 4 (was 15).
        float ts[8]; int ti[8];
        #pragma unroll
        for (int m = 0; m < 8; m++)
            TMIN(s[2 * m], 2 * m, s[2 * m + 1], 2 * m + 1, ts[m], ti[m]);
        float us[4]; int ui[4];
        #pragma unroll
        for (int m = 0; m < 4; m++)
            TMIN(ts[2 * m], ti[2 * m], ts[2 * m + 1], ti[2 * m + 1], us[m], ui[m]);
        float vs0, vs1; int vi0, vi1;
        TMIN(us[0], ui[0], us[1], ui[1], vs0, vi0);
        TMIN(us[2], ui[2], us[3], ui[3], vs1, vi1);
        float fs; int bi;
        TMIN(vs0, vi0, vs1, vi1, fs, bi);
        (void)fs;

        float4 col = spal4[bi];
        r0[i] = col.x; r1[i] = col.y; r2[i] = col.z;

        // Retire first half's results early to cap register pressure.
        if (i == 3) {
            float* obase = out + (size_t)b * 3 * HW + r;
            reinterpret_cast<float4*>(obase)[0]          = make_float4(r0[0], r0[1], r0[2], r0[3]);
            reinterpret_cast<float4*>(obase + HW)[0]     = make_float4(r1[0], r1[1], r1[2], r1[3]);
            reinterpret_cast<float4*>(obase + 2 * HW)[0] = make_float4(r2[0], r2[1], r2[2], r2[3]);
        }
    }

    float* obase = out + (size_t)b * 3 * HW + r;
    reinterpret_cast<float4*>(obase)[1]          = make_float4(r0[4], r0[5], r0[6], r0[7]);
    reinterpret_cast<float4*>(obase + HW)[1]     = make_float4(r1[4], r1[5], r1[6], r1[7]);
    reinterpret_cast<float4*>(obase + 2 * HW)[1] = make_float4(r2[4], r2[5], r2[6], r2[7]);
}

extern "C" void kernel_launch(void* const* d_in, const int* in_sizes, int n_in,
                              void* d_out, int out_size) {
    const float* x  = (const float*)d_in[0];
    float* out = (float*)d_out;

    gather_kernel<<<1, 228>>>((const float*)d_in[1], (const float*)d_in[2],
                              (const float*)d_in[3], (const float*)d_in[4]);

    void* stage_ptr = nullptr;
    cudaGetSymbolAddress(&stage_ptr, g_stage);   // address query only, no stream op
    cudaMemcpyToSymbolAsync(cAll, stage_ptr, 228 * sizeof(float), 0,
                            cudaMemcpyDeviceToDevice, 0);

    cq_kernel<<<NTHR8 / 256, 256>>>(x, out);
}